// round 13
// baseline (speedup 1.0000x reference)
#include <cuda_runtime.h>
#include <cuda_fp16.h>
#include <cstdint>

// ---------------------------------------------------------------------------
// MinGRU layer: B=4, T=4096, D=1024, Di=2048   (legacy mma.sync fp16 path —
// harness compiles via compute_103 virtual arch, so tcgen05 is unavailable)
//   hg = x @ W_hg ; c = sigmoid(-gate); v = sigmoid(gate)*G(hidden)
//   h_t = c_t*h_{t-1} + v_t, h_{-1} = max(prev_hidden, 1e-8)
//   out = h @ W_out ; next_hidden = h[:, T-1]
// R13: GEMM1 CTA doubled to 128x128 channels (256 threads, 8 warps, B-tile
//      256 n-rows) so epilogue/prologue amortize over 2x MACs — matching
//      GEMM2's per-CTA efficiency (1.29 vs 1.0 TFLOP/s per slot).
// ---------------------------------------------------------------------------

constexpr int BBATCH = 4;
constexpr int TSEQ   = 4096;
constexpr int DDIM   = 1024;
constexpr int DI     = 2048;
constexpr int MROWS  = BBATCH * TSEQ;      // 16384
constexpr int NCHUNK = 32;
constexpr int CHLEN  = TSEQ / NCHUNK;      // 128 == GEMM1 M-tile
constexpr int NCHAN  = BBATCH * DI;        // 8192

// ---- scratch (static __device__ globals; no allocation) --------------------
__device__ __half g_xh [(size_t)MROWS * DDIM];      //  32 MB  fp16 x
__device__ __half g_whT[(size_t)(2 * DI) * DDIM];   //   8 MB  W_hg^T fp16 [4096][1024]
__device__ __half g_woT[(size_t)DDIM * DI];         //   4 MB  W_out^T fp16 [1024][2048]
__device__ __half g_c  [(size_t)MROWS * DI];        //  64 MB  fp16 c
__device__ __half g_v  [(size_t)MROWS * DI];        //  64 MB  fp16 v
__device__ __half g_hh [(size_t)MROWS * DI];        //  64 MB  fp16 h
__device__ float  g_chC[NCHAN * NCHUNK];
__device__ float  g_chV[NCHAN * NCHUNK];

// ---- helpers ---------------------------------------------------------------
__device__ __forceinline__ void cp16(const __half* dst_smem, const __half* src_gmem) {
    uint32_t a = (uint32_t)__cvta_generic_to_shared(dst_smem);
    asm volatile("cp.async.ca.shared.global [%0], [%1], 16;\n" :: "r"(a), "l"(src_gmem));
}
#define CP_COMMIT() asm volatile("cp.async.commit_group;\n")
#define CP_WAIT1()  asm volatile("cp.async.wait_group 1;\n")
#define CP_WAIT0()  asm volatile("cp.async.wait_group 0;\n")

__device__ __forceinline__ void mma_f16(float d[4], const uint32_t a[4], const uint32_t b[2]) {
    asm volatile(
        "mma.sync.aligned.m16n8k16.row.col.f32.f16.f16.f32 "
        "{%0,%1,%2,%3}, {%4,%5,%6,%7}, {%8,%9}, {%0,%1,%2,%3};\n"
        : "+f"(d[0]), "+f"(d[1]), "+f"(d[2]), "+f"(d[3])
        : "r"(a[0]), "r"(a[1]), "r"(a[2]), "r"(a[3]), "r"(b[0]), "r"(b[1]));
}

__device__ __forceinline__ void ldsm4(uint32_t r[4], const __half* p) {
    uint32_t a = (uint32_t)__cvta_generic_to_shared(p);
    asm volatile("ldmatrix.sync.aligned.m8n8.x4.shared.b16 {%0,%1,%2,%3}, [%4];"
                 : "=r"(r[0]), "=r"(r[1]), "=r"(r[2]), "=r"(r[3]) : "r"(a));
}

__device__ __forceinline__ float sigmoidf_fast(float x) {
    return 1.0f / (1.0f + __expf(-x));
}

// ---- kernel 0a: x fp32 -> fp16 (rne) ---------------------------------------
__global__ void k_conv_x(const float4* __restrict__ x) {
    int i = blockIdx.x * blockDim.x + threadIdx.x;   // handles 8 floats
    float4 a = x[2 * i], b = x[2 * i + 1];
    __half2 h0 = __floats2half2_rn(a.x, a.y);
    __half2 h1 = __floats2half2_rn(a.z, a.w);
    __half2 h2 = __floats2half2_rn(b.x, b.y);
    __half2 h3 = __floats2half2_rn(b.z, b.w);
    uint4 o;
    o.x = *(uint32_t*)&h0; o.y = *(uint32_t*)&h1;
    o.z = *(uint32_t*)&h2; o.w = *(uint32_t*)&h3;
    ((uint4*)g_xh)[i] = o;
}

// ---- kernel 0b/0c: weight transpose + fp16 convert -------------------------
__global__ void k_trans_whg(const float* __restrict__ w) {   // [1024][4096] -> [4096][1024]
    __shared__ float t[32][33];
    int bx = blockIdx.x * 32, by = blockIdx.y * 32;
    int x = threadIdx.x, y = threadIdx.y;
    #pragma unroll
    for (int i = 0; i < 32; i += 8)
        t[y + i][x] = w[(size_t)(by + y + i) * (2 * DI) + bx + x];
    __syncthreads();
    #pragma unroll
    for (int i = 0; i < 32; i += 8)
        g_whT[(size_t)(bx + y + i) * DDIM + by + x] = __float2half_rn(t[x][y + i]);
}

__global__ void k_trans_wout(const float* __restrict__ w) {  // [2048][1024] -> [1024][2048]
    __shared__ float t[32][33];
    int bx = blockIdx.x * 32, by = blockIdx.y * 32;
    int x = threadIdx.x, y = threadIdx.y;
    #pragma unroll
    for (int i = 0; i < 32; i += 8)
        t[y + i][x] = w[(size_t)(by + y + i) * DDIM + bx + x];
    __syncthreads();
    #pragma unroll
    for (int i = 0; i < 32; i += 8)
        g_woT[(size_t)(bx + y + i) * DI + by + x] = __float2half_rn(t[x][y + i]);
}

// ---- GEMM tiling constants --------------------------------------------------
constexpr int BM     = 128;
constexpr int BK     = 64;                      // halves per k-tile
constexpr int STRH   = 72;                      // smem row stride in halves (144B, conflict-free)
// GEMM1 (big CTA): A 128 rows, B 256 n-rows
constexpr int A1TILE = BM * STRH;
constexpr int B1TILE = 256 * STRH;
constexpr int G1_SMEM = 2 * (A1TILE + B1TILE) * 2;   // 110592
constexpr int HSTR1  = 136;                     // epilogue fp16 stage stride (halves)
static_assert(2 * 128 * HSTR1 * 2 <= G1_SMEM, "epi1 fits");
// GEMM2 (unchanged R8/R12): A 128 rows, B 128 n-rows
constexpr int ATILE = BM * STRH;
constexpr int BTILE = 128 * STRH;
constexpr int G2_SMEM = 2 * (ATILE + BTILE) * 2;     // 73728
constexpr int ESTR2 = 132;                      // 128x128 out tile (floats)
static_assert(128 * ESTR2 * 4 <= G2_SMEM, "epi2 fits");

// ---- kernel 1: GEMM1 hg = x @ W_hg (fp16 mma), fused c/v + chunk reduce ----
// CTA: 128 rows x 128 channels. 8 warps, warp tile 64x64 (2x4 warp grid).
// B smem rows (N-major [n][k]), group g = row>>6 (4 groups of 64):
//   rows g*64 +  0..31 : hidden channels n0+g*32 .. +31
//   rows g*64 + 32..63 : gate   channels n0+g*32 .. +31
__device__ __forceinline__ void g1_load(int tid, int m0, int n0, int kt,
                                        __half* as, __half* bs) {
    const int k0 = kt * BK;
    #pragma unroll
    for (int q = 0; q < 4; q++) {            // A: 128 rows x 128B = 1024 x 16B
        int idx = tid + q * 256;
        int row = idx >> 3, c16 = (idx & 7) * 8;
        cp16(&as[row * STRH + c16], &g_xh[(size_t)(m0 + row) * DDIM + k0 + c16]);
    }
    #pragma unroll
    for (int q = 0; q < 8; q++) {            // B: 256 n-rows x 128B = 2048 x 16B
        int idx = tid + q * 256;
        int row = idx >> 3, c16 = (idx & 7) * 8;
        int within = row & 63;
        int chan = n0 + ((row >> 6) << 5) + (within & 31);
        int grow = (within & 32) ? (DI + chan) : chan;
        cp16(&bs[row * STRH + c16], &g_whT[(size_t)grow * DDIM + k0 + c16]);
    }
}

__global__ void __launch_bounds__(256, 1) k_gemm1() {
    const int m0 = blockIdx.y * BM;
    const int n0 = blockIdx.x * 128;
    const int tid = threadIdx.x;
    const int wid = tid >> 5, lane = tid & 31;
    const int wm = wid & 1, wn = wid >> 1;       // 2 x 4 warp grid
    const int grp = lane >> 2, tg = lane & 3;

    extern __shared__ char smraw[];
    __half* As = (__half*)smraw;                 // [2][A1TILE]
    __half* Bs = As + 2 * A1TILE;                // [2][B1TILE]
    __shared__ float sC2[128], sV2[128];         // chunk-reduce combine buffer

    float acc[4][8][4];
    #pragma unroll
    for (int a = 0; a < 4; a++)
        #pragma unroll
        for (int b = 0; b < 8; b++)
            #pragma unroll
            for (int r = 0; r < 4; r++) acc[a][b][r] = 0.f;

    // ldmatrix per-lane source rows/col-offsets
    const int a_row  = wm * 64 + (lane & 15);
    const int a_koff = (lane >> 4) << 3;
    const int b_row  = wn * 64 + (lane & 7) + ((lane >> 4) << 3);
    const int b_koff = ((lane >> 3) & 1) << 3;

    g1_load(tid, m0, n0, 0, As, Bs);
    CP_COMMIT();

    constexpr int NKT = DDIM / BK;               // 16
    #pragma unroll 1
    for (int kt = 0; kt < NKT; kt++) {
        const int buf = kt & 1;
        if (kt + 1 < NKT) {
            g1_load(tid, m0, n0, kt + 1, As + (buf ^ 1) * A1TILE, Bs + (buf ^ 1) * B1TILE);
            CP_COMMIT();
            CP_WAIT1();
        } else {
            CP_WAIT0();
        }
        __syncthreads();
        const __half* as = As + buf * A1TILE;
        const __half* bs = Bs + buf * B1TILE;
        #pragma unroll
        for (int ks = 0; ks < 4; ks++) {
            const int k = ks * 16;
            uint32_t a[4][4], b[8][2];
            #pragma unroll
            for (int mm = 0; mm < 4; mm++)
                ldsm4(a[mm], &as[(a_row + mm * 16) * STRH + k + a_koff]);
            #pragma unroll
            for (int jp = 0; jp < 4; jp++) {
                uint32_t t[4];
                ldsm4(t, &bs[(b_row + jp * 16) * STRH + k + b_koff]);
                b[2 * jp][0] = t[0]; b[2 * jp][1] = t[1];
                b[2 * jp + 1][0] = t[2]; b[2 * jp + 1][1] = t[3];
            }
            #pragma unroll
            for (int mm = 0; mm < 4; mm++)
                #pragma unroll
                for (int jn = 0; jn < 8; jn++)
                    mma_f16(acc[mm][jn], a[mm], b[jn]);
        }
        __syncthreads();
    }

    // ---- epilogue: c/v -> fp16 smem stage; coalesced stores; serial reduce -
    // jn 0-3 = hidden (warp B-rows 0-31 of its 64-group), jn 4-7 = gate.
    __half* sch = (__half*)smraw;         // [128][HSTR1]
    __half* svh = sch + 128 * HSTR1;      // [128][HSTR1]
    #pragma unroll
    for (int mm = 0; mm < 4; mm++)
        #pragma unroll
        for (int jn = 0; jn < 4; jn++)
            #pragma unroll
            for (int r = 0; r < 4; r++) {
                float hv = acc[mm][jn][r];
                float gv = acc[mm][jn + 4][r];
                int rl = wm * 64 + mm * 16 + grp + ((r >> 1) << 3);
                int cl = wn * 32 + jn * 8 + tg * 2 + (r & 1);
                float e  = __expf(gv);
                float ci = 1.0f / (1.0f + e);        // sigmoid(-g)
                float z  = 1.0f - ci;                // sigmoid(g)
                float G  = (hv >= 0.0f) ? (hv + 0.5f) : sigmoidf_fast(hv);
                sch[rl * HSTR1 + cl] = __float2half_rn(ci);
                svh[rl * HSTR1 + cl] = __float2half_rn(z * G);
            }
    __syncthreads();

    // coalesced 8B fp16 writes of the 128x128 c/v tiles
    #pragma unroll
    for (int q = 0; q < 16; q++) {
        int idx = tid + q * 256;               // 0..4095
        int row = idx >> 5, c4 = (idx & 31) * 4;
        uint2 cpk = *(const uint2*)&sch[row * HSTR1 + c4];
        uint2 vpk = *(const uint2*)&svh[row * HSTR1 + c4];
        *(uint2*)&g_c[(size_t)(m0 + row) * DI + n0 + c4] = cpk;
        *(uint2*)&g_v[(size_t)(m0 + row) * DI + n0 + c4] = vpk;
    }

    // thread-serial chunk reduce on the SAME fp16 values (rows = time order).
    // thread t<128: col t, rows 0-63; t>=128: col t-128, rows 64-127.
    // Compose: C = C1*C2, V = C2*V1 + V2  (later o earlier).
    {
        const int batch = m0 >> 12;            // m0 / 4096
        const int chunk = (m0 & 4095) >> 7;    // (m0 % 4096) / 128
        const int col   = tid & 127;
        const int rb    = (tid >> 7) << 6;     // 0 or 64
        float C = 1.f, V = 0.f;
        #pragma unroll 8
        for (int r = 0; r < 64; r++) {
            float c_ = __half2float(sch[(rb + r) * HSTR1 + col]);
            float v_ = __half2float(svh[(rb + r) * HSTR1 + col]);
            V = fmaf(c_, V, v_);
            C *= c_;
        }
        if (tid >= 128) { sC2[col] = C; sV2[col] = V; }
        __syncthreads();
        if (tid < 128) {
            float C2 = sC2[col], V2 = sV2[col];
            int ch = batch * DI + n0 + col;
            g_chC[ch * NCHUNK + chunk] = C * C2;
            g_chV[ch * NCHUNK + chunk] = fmaf(C2, V, V2);
        }
    }
}

// ---- kernel 4: prefix over chunk aggregates + replay (2 channels/thread) ---
// grid (NCHAN/2/256, NCHUNK); no separate chunk_scan kernel.
__global__ void k_scan_apply(const float* __restrict__ prev_hidden,
                             float* __restrict__ next_hidden) {
    int p = blockIdx.x * blockDim.x + threadIdx.x;   // pair 0..4095
    int chunk = blockIdx.y;
    int ch0 = p * 2;
    int b = ch0 >> 11, j = ch0 & (DI - 1);

    // chunk-start state via prefix over aggregates (redundant per block, cheap)
    float h0 = fmaxf(prev_hidden[ch0], 1e-8f);
    float h1 = fmaxf(prev_hidden[ch0 + 1], 1e-8f);
    #pragma unroll 1
    for (int k = 0; k < chunk; k++) {
        h0 = fmaf(g_chC[ch0 * NCHUNK + k], h0, g_chV[ch0 * NCHUNK + k]);
        h1 = fmaf(g_chC[(ch0 + 1) * NCHUNK + k], h1, g_chV[(ch0 + 1) * NCHUNK + k]);
    }

    size_t base2 = (((size_t)(b * TSEQ + chunk * CHLEN)) * DI + j) >> 1;  // half2 units
    const __half2* c2 = (const __half2*)g_c;
    const __half2* v2 = (const __half2*)g_v;
    __half2* hh2 = (__half2*)g_hh;
    #pragma unroll 4
    for (int t = 0; t < CHLEN; t++) {
        size_t o = base2 + (size_t)t * (DI / 2);
        float2 cf = __half22float2(c2[o]);
        float2 vf = __half22float2(v2[o]);
        h0 = fmaf(cf.x, h0, vf.x);
        h1 = fmaf(cf.y, h1, vf.y);
        hh2[o] = __floats2half2_rn(h0, h1);
    }
    if (chunk == NCHUNK - 1) {
        next_hidden[ch0]     = h0;
        next_hidden[ch0 + 1] = h1;
    }
}

// ---- kernel 5: GEMM2 out = h @ W_out (fp16 mma) ----------------------------
__device__ __forceinline__ void g2_load(int tid, int m0, int n0, int kt,
                                        __half* as, __half* bs) {
    const int k0 = kt * BK;
    #pragma unroll
    for (int q = 0; q < 8; q++) {
        int idx = tid + q * 128;
        int row = idx >> 3, c16 = (idx & 7) * 8;
        cp16(&as[row * STRH + c16], &g_hh[(size_t)(m0 + row) * DI + k0 + c16]);
    }
    #pragma unroll
    for (int q = 0; q < 8; q++) {
        int idx = tid + q * 128;
        int row = idx >> 3, c16 = (idx & 7) * 8;
        cp16(&bs[row * STRH + c16], &g_woT[(size_t)(n0 + row) * DI + k0 + c16]);
    }
}

__global__ void __launch_bounds__(128, 2) k_gemm2(float* __restrict__ out) {
    const int m0 = blockIdx.y * BM;
    const int n0 = blockIdx.x * 128;
    const int tid = threadIdx.x;
    const int wid = tid >> 5, lane = tid & 31;
    const int wm = wid & 1, wn = wid >> 1;       // 2 x 2 warp grid, 64x64 tiles
    const int grp = lane >> 2, tg = lane & 3;

    extern __shared__ char smraw[];
    __half* As = (__half*)smraw;
    __half* Bs = As + 2 * ATILE;

    float acc[4][8][4];
    #pragma unroll
    for (int a = 0; a < 4; a++)
        #pragma unroll
        for (int b = 0; b < 8; b++)
            #pragma unroll
            for (int r = 0; r < 4; r++) acc[a][b][r] = 0.f;

    const int a_row  = wm * 64 + (lane & 15);
    const int a_koff = (lane >> 4) << 3;
    const int b_row  = wn * 64 + (lane & 7) + ((lane >> 4) << 3);
    const int b_koff = ((lane >> 3) & 1) << 3;

    g2_load(tid, m0, n0, 0, As, Bs);
    CP_COMMIT();

    constexpr int NKT = DI / BK;                 // 32
    #pragma unroll 1
    for (int kt = 0; kt < NKT; kt++) {
        const int buf = kt & 1;
        if (kt + 1 < NKT) {
            g2_load(tid, m0, n0, kt + 1, As + (buf ^ 1) * ATILE, Bs + (buf ^ 1) * BTILE);
            CP_COMMIT();
            CP_WAIT1();
        } else {
            CP_WAIT0();
        }
        __syncthreads();
        const __half* as = As + buf * ATILE;
        const __half* bs = Bs + buf * BTILE;
        #pragma unroll
        for (int ks = 0; ks < 4; ks++) {
            const int k = ks * 16;
            uint32_t a[4][4], b[8][2];
            #pragma unroll
            for (int mm = 0; mm < 4; mm++)
                ldsm4(a[mm], &as[(a_row + mm * 16) * STRH + k + a_koff]);
            #pragma unroll
            for (int jp = 0; jp < 4; jp++) {
                uint32_t t[4];
                ldsm4(t, &bs[(b_row + jp * 16) * STRH + k + b_koff]);
                b[2 * jp][0] = t[0]; b[2 * jp][1] = t[1];
                b[2 * jp + 1][0] = t[2]; b[2 * jp + 1][1] = t[3];
            }
            #pragma unroll
            for (int mm = 0; mm < 4; mm++)
                #pragma unroll
                for (int jn = 0; jn < 8; jn++)
                    mma_f16(acc[mm][jn], a[mm], b[jn]);
        }
        __syncthreads();
    }

    // ---- epilogue: stage 128x128 tile in smem, coalesced float4 stores -----
    float* so = (float*)smraw;                 // [128][ESTR2]
    #pragma unroll
    for (int mm = 0; mm < 4; mm++)
        #pragma unroll
        for (int jn = 0; jn < 8; jn++)
            #pragma unroll
            for (int r = 0; r < 4; r++) {
                int rl = wm * 64 + mm * 16 + grp + ((r >> 1) << 3);
                int cl = wn * 64 + jn * 8 + tg * 2 + (r & 1);
                so[rl * ESTR2 + cl] = acc[mm][jn][r];
            }
    __syncthreads();
    #pragma unroll
    for (int q = 0; q < 32; q++) {
        int idx = tid + q * 128;               // 0..4095
        int row = idx >> 5, c4 = (idx & 31) * 4;
        float4 vv = *(const float4*)&so[row * ESTR2 + c4];
        *(float4*)&out[(size_t)(m0 + row) * DDIM + n0 + c4] = vv;
    }
}

// ---------------------------------------------------------------------------
extern "C" void kernel_launch(void* const* d_in, const int* in_sizes, int n_in,
                              void* d_out, int out_size) {
    const float* x    = (const float*)d_in[0];   // (4, 4096, 1024)
    const float* prev = (const float*)d_in[1];   // (4, 2048)
    const float* whg  = (const float*)d_in[2];   // (1024, 4096)
    const float* wout = (const float*)d_in[3];   // (2048, 1024)
    float* out = (float*)d_out;                  // out (16777216) + next_hidden (8192)
    float* next_hidden = out + (size_t)MROWS * DDIM;

    cudaFuncSetAttribute(k_gemm1, cudaFuncAttributeMaxDynamicSharedMemorySize, G1_SMEM);
    cudaFuncSetAttribute(k_gemm2, cudaFuncAttributeMaxDynamicSharedMemorySize, G2_SMEM);

    // 0) fp16 conversions (rne) + weight transposes to N-major
    k_conv_x<<<(MROWS * DDIM / 8) / 256, 256>>>((const float4*)x);
    {
        dim3 b(32, 8);
        k_trans_whg <<<dim3(2 * DI / 32, DDIM / 32), b>>>(whg);
        k_trans_wout<<<dim3(DDIM / 32,  DI / 32),   b>>>(wout);
    }
    // 1) GEMM1 (fp16 mma, 128x128-ch CTA) + fp16 c/v epilogue + chunk reduce
    {
        dim3 grid(DI / 128, MROWS / BM);         // 16 x 128
        k_gemm1<<<grid, 256, G1_SMEM>>>();
    }
    // 2) prefix + replay -> h (fp16), next_hidden
    {
        dim3 grid((NCHAN / 2) / 256, NCHUNK);    // 16 x 32
        k_scan_apply<<<grid, 256>>>(prev, next_hidden);
    }
    // 3) GEMM2 (fp16 mma) -> out
    {
        dim3 grid(DDIM / 128, MROWS / BM);       // 8 x 128
        k_gemm2<<<grid, 128, G2_SMEM>>>(out);
    }
}

// round 14
// speedup vs baseline: 1.0768x; 1.0768x over previous
#include <cuda_runtime.h>
#include <cuda_fp16.h>
#include <cstdint>

// ---------------------------------------------------------------------------
// MinGRU layer: B=4, T=4096, D=1024, Di=2048   (legacy mma.sync fp16 path —
// harness compiles via compute_103 virtual arch, so tcgen05 is unavailable)
//   hg = x @ W_hg ; c = sigmoid(-gate); v = sigmoid(gate)*G(hidden)
//   h_t = c_t*h_{t-1} + v_t, h_{-1} = max(prev_hidden, 1e-8)
//   out = h @ W_out ; next_hidden = h[:, T-1]
// R14: GEMMs = R12 exactly (best measured; 2 CTAs/SM is load-bearing).
//      All prep (x->fp16, both weight transposes) merged into ONE kernel.
// ---------------------------------------------------------------------------

constexpr int BBATCH = 4;
constexpr int TSEQ   = 4096;
constexpr int DDIM   = 1024;
constexpr int DI     = 2048;
constexpr int MROWS  = BBATCH * TSEQ;      // 16384
constexpr int NCHUNK = 32;
constexpr int CHLEN  = TSEQ / NCHUNK;      // 128 == GEMM1 M-tile
constexpr int NCHAN  = BBATCH * DI;        // 8192

// ---- scratch (static __device__ globals; no allocation) --------------------
__device__ __half g_xh [(size_t)MROWS * DDIM];      //  32 MB  fp16 x
__device__ __half g_whT[(size_t)(2 * DI) * DDIM];   //   8 MB  W_hg^T fp16 [4096][1024]
__device__ __half g_woT[(size_t)DDIM * DI];         //   4 MB  W_out^T fp16 [1024][2048]
__device__ __half g_c  [(size_t)MROWS * DI];        //  64 MB  fp16 c
__device__ __half g_v  [(size_t)MROWS * DI];        //  64 MB  fp16 v
__device__ __half g_hh [(size_t)MROWS * DI];        //  64 MB  fp16 h
__device__ float  g_chC[NCHAN * NCHUNK];
__device__ float  g_chV[NCHAN * NCHUNK];

// ---- helpers ---------------------------------------------------------------
__device__ __forceinline__ void cp16(const __half* dst_smem, const __half* src_gmem) {
    uint32_t a = (uint32_t)__cvta_generic_to_shared(dst_smem);
    asm volatile("cp.async.ca.shared.global [%0], [%1], 16;\n" :: "r"(a), "l"(src_gmem));
}
#define CP_COMMIT() asm volatile("cp.async.commit_group;\n")
#define CP_WAIT1()  asm volatile("cp.async.wait_group 1;\n")
#define CP_WAIT0()  asm volatile("cp.async.wait_group 0;\n")

__device__ __forceinline__ void mma_f16(float d[4], const uint32_t a[4], const uint32_t b[2]) {
    asm volatile(
        "mma.sync.aligned.m16n8k16.row.col.f32.f16.f16.f32 "
        "{%0,%1,%2,%3}, {%4,%5,%6,%7}, {%8,%9}, {%0,%1,%2,%3};\n"
        : "+f"(d[0]), "+f"(d[1]), "+f"(d[2]), "+f"(d[3])
        : "r"(a[0]), "r"(a[1]), "r"(a[2]), "r"(a[3]), "r"(b[0]), "r"(b[1]));
}

__device__ __forceinline__ void ldsm4(uint32_t r[4], const __half* p) {
    uint32_t a = (uint32_t)__cvta_generic_to_shared(p);
    asm volatile("ldmatrix.sync.aligned.m8n8.x4.shared.b16 {%0,%1,%2,%3}, [%4];"
                 : "=r"(r[0]), "=r"(r[1]), "=r"(r[2]), "=r"(r[3]) : "r"(a));
}

__device__ __forceinline__ float sigmoidf_fast(float x) {
    return 1.0f / (1.0f + __expf(-x));
}

__device__ __forceinline__ float rnd_h(float x) {       // round to fp16 grid
    return __half2float(__float2half_rn(x));
}

// ---- kernel 0: merged prep — x->fp16, W_hg^T, W_out^T (one launch) ---------
// blockIdx.x segments: [0,NCX) conv_x | [NCX,NCX+NWT) whg tiles | rest wout.
constexpr int NCX = (MROWS * DDIM / 8) / 256;            // 8192 blocks
constexpr int NWT = (2 * DI / 32) * (DDIM / 32);         // 4096 tiles (128 x 32)
constexpr int NOT_ = (DDIM / 32) * (DI / 32);            // 2048 tiles (32 x 64)

__global__ void k_prep(const float* __restrict__ x,
                       const float* __restrict__ whg,
                       const float* __restrict__ wout) {
    const int blk = blockIdx.x;
    const int tid = threadIdx.x;

    if (blk < NCX) {                         // ---- x fp32 -> fp16 (rne), 8/thread
        int i = blk * 256 + tid;
        const float4* xv = (const float4*)x;
        float4 a = xv[2 * i], b = xv[2 * i + 1];
        __half2 h0 = __floats2half2_rn(a.x, a.y);
        __half2 h1 = __floats2half2_rn(a.z, a.w);
        __half2 h2 = __floats2half2_rn(b.x, b.y);
        __half2 h3 = __floats2half2_rn(b.z, b.w);
        uint4 o;
        o.x = *(uint32_t*)&h0; o.y = *(uint32_t*)&h1;
        o.z = *(uint32_t*)&h2; o.w = *(uint32_t*)&h3;
        ((uint4*)g_xh)[i] = o;
        return;
    }

    __shared__ float t[32][33];
    const int y = tid >> 5, xl = tid & 31;   // 8 x 32 thread layout

    if (blk < NCX + NWT) {                   // ---- W_hg [1024][4096] -> T fp16
        int tile = blk - NCX;
        int bx = (tile & 127) * 32;          // over 4096
        int by = (tile >> 7) * 32;           // over 1024
        #pragma unroll
        for (int i = 0; i < 32; i += 8)
            t[y + i][xl] = whg[(size_t)(by + y + i) * (2 * DI) + bx + xl];
        __syncthreads();
        #pragma unroll
        for (int i = 0; i < 32; i += 8)
            g_whT[(size_t)(bx + y + i) * DDIM + by + xl] = __float2half_rn(t[xl][y + i]);
    } else {                                 // ---- W_out [2048][1024] -> T fp16
        int tile = blk - NCX - NWT;
        int bx = (tile & 31) * 32;           // over 1024
        int by = (tile >> 5) * 32;           // over 2048
        #pragma unroll
        for (int i = 0; i < 32; i += 8)
            t[y + i][xl] = wout[(size_t)(by + y + i) * DDIM + bx + xl];
        __syncthreads();
        #pragma unroll
        for (int i = 0; i < 32; i += 8)
            g_woT[(size_t)(bx + y + i) * DI + by + xl] = __float2half_rn(t[xl][y + i]);
    }
}

// ---- GEMM tiling constants (R12 — best measured) ----------------------------
constexpr int BM    = 128;
constexpr int BK    = 64;                       // halves per k-tile
constexpr int STRH  = 72;                       // smem row stride in halves (144B, conflict-free)
constexpr int ATILE = BM * STRH;                // halves per A buffer
constexpr int BTILE = 128 * STRH;               // halves per B buffer (128 n-rows)
constexpr int SMEM_GEMM_BYTES = 2 * (ATILE + BTILE) * 2;  // 73728
// epilogue staging (reuses the same dynamic smem):
constexpr int ESTR1 = 68;   // 128x64 c + v tiles (floats)
constexpr int ESTR2 = 132;  // 128x128 out tile  (floats)
static_assert(2 * 128 * ESTR1 * 4 <= SMEM_GEMM_BYTES, "epi1 fits");
static_assert(128 * ESTR2 * 4 <= SMEM_GEMM_BYTES, "epi2 fits");

// ---- kernel 1: GEMM1 hg = x @ W_hg (fp16 mma), fused c/v + chunk reduce ----
// CTA: 128 rows x 64 channels. 4 warps, warp tile 64x64 (2x2 warp grid).
// B smem rows (N-major [n][k]): 0-31 hid(n0..n0+31), 32-63 gate(n0..n0+31),
//                               64-95 hid(n0+32..), 96-127 gate(n0+32..)
__device__ __forceinline__ void g1_load(int tid, int m0, int n0, int kt,
                                        __half* as, __half* bs) {
    const int k0 = kt * BK;
    #pragma unroll
    for (int q = 0; q < 8; q++) {            // A: 128 rows x 128B
        int idx = tid + q * 128;
        int row = idx >> 3, c16 = (idx & 7) * 8;
        cp16(&as[row * STRH + c16], &g_xh[(size_t)(m0 + row) * DDIM + k0 + c16]);
    }
    #pragma unroll
    for (int q = 0; q < 8; q++) {            // B: 128 n-rows x 128B
        int idx = tid + q * 128;
        int row = idx >> 3, c16 = (idx & 7) * 8;
        int base = n0 + ((row >> 6) << 5) + (row & 31);
        int grow = ((row >> 5) & 1) ? (DI + base) : base;
        cp16(&bs[row * STRH + c16], &g_whT[(size_t)grow * DDIM + k0 + c16]);
    }
}

__global__ void __launch_bounds__(128, 2) k_gemm1() {
    const int m0 = blockIdx.y * BM;
    const int n0 = blockIdx.x * 64;
    const int tid = threadIdx.x;
    const int wid = tid >> 5, lane = tid & 31;
    const int wm = wid & 1, wn = wid >> 1;       // 2 x 2 warp grid
    const int grp = lane >> 2, tg = lane & 3;

    extern __shared__ char smraw[];
    __half* As = (__half*)smraw;                 // [2][ATILE]
    __half* Bs = As + 2 * ATILE;                 // [2][BTILE]
    __shared__ float sC2[64], sV2[64];           // chunk-reduce combine buffer

    float acc[4][8][4];
    #pragma unroll
    for (int a = 0; a < 4; a++)
        #pragma unroll
        for (int b = 0; b < 8; b++)
            #pragma unroll
            for (int r = 0; r < 4; r++) acc[a][b][r] = 0.f;

    // ldmatrix per-lane source rows/col-offsets
    const int a_row  = wm * 64 + (lane & 15);
    const int a_koff = (lane >> 4) << 3;
    const int b_row  = wn * 64 + (lane & 7) + ((lane >> 4) << 3);
    const int b_koff = ((lane >> 3) & 1) << 3;

    g1_load(tid, m0, n0, 0, As, Bs);
    CP_COMMIT();

    constexpr int NKT = DDIM / BK;               // 16
    #pragma unroll 1
    for (int kt = 0; kt < NKT; kt++) {
        const int buf = kt & 1;
        if (kt + 1 < NKT) {
            g1_load(tid, m0, n0, kt + 1, As + (buf ^ 1) * ATILE, Bs + (buf ^ 1) * BTILE);
            CP_COMMIT();
            CP_WAIT1();
        } else {
            CP_WAIT0();
        }
        __syncthreads();
        const __half* as = As + buf * ATILE;
        const __half* bs = Bs + buf * BTILE;
        #pragma unroll
        for (int ks = 0; ks < 4; ks++) {
            const int k = ks * 16;
            uint32_t a[4][4], b[8][2];
            #pragma unroll
            for (int mm = 0; mm < 4; mm++)
                ldsm4(a[mm], &as[(a_row + mm * 16) * STRH + k + a_koff]);
            #pragma unroll
            for (int jp = 0; jp < 4; jp++) {
                uint32_t t[4];
                ldsm4(t, &bs[(b_row + jp * 16) * STRH + k + b_koff]);
                b[2 * jp][0] = t[0]; b[2 * jp][1] = t[1];
                b[2 * jp + 1][0] = t[2]; b[2 * jp + 1][1] = t[3];
            }
            #pragma unroll
            for (int mm = 0; mm < 4; mm++)
                #pragma unroll
                for (int jn = 0; jn < 8; jn++)
                    mma_f16(acc[mm][jn], a[mm], b[jn]);
        }
        __syncthreads();
    }

    // ---- epilogue: c/v (rounded to fp16 grid) -> smem; coalesced fp16 store;
    //      thread-serial chunk reduce on the SAME rounded values --------------
    float* sc = (float*)smraw;            // [128][ESTR1]
    float* sv = sc + 128 * ESTR1;         // [128][ESTR1]
    #pragma unroll
    for (int mm = 0; mm < 4; mm++)
        #pragma unroll
        for (int jn = 0; jn < 4; jn++)
            #pragma unroll
            for (int r = 0; r < 4; r++) {
                float hv = acc[mm][jn][r];
                float gv = acc[mm][jn + 4][r];
                int rl = wm * 64 + mm * 16 + grp + ((r >> 1) << 3);
                int cl = wn * 32 + jn * 8 + tg * 2 + (r & 1);
                float e  = __expf(gv);
                float ci = 1.0f / (1.0f + e);        // sigmoid(-g)
                float z  = 1.0f - ci;                // sigmoid(g)
                float G  = (hv >= 0.0f) ? (hv + 0.5f) : sigmoidf_fast(hv);
                sc[rl * ESTR1 + cl] = rnd_h(ci);
                sv[rl * ESTR1 + cl] = rnd_h(z * G);
            }
    __syncthreads();

    // coalesced 8B fp16 writes of the 128x64 c/v tiles
    #pragma unroll
    for (int q = 0; q < 16; q++) {
        int idx = tid + q * 128;               // 0..2047
        int row = idx >> 4, c4 = (idx & 15) * 4;
        float4 vc = *(const float4*)&sc[row * ESTR1 + c4];
        float4 vv = *(const float4*)&sv[row * ESTR1 + c4];
        __half2 c01 = __floats2half2_rn(vc.x, vc.y);
        __half2 c23 = __floats2half2_rn(vc.z, vc.w);
        __half2 v01 = __floats2half2_rn(vv.x, vv.y);
        __half2 v23 = __floats2half2_rn(vv.z, vv.w);
        uint2 cpk = make_uint2(*(uint32_t*)&c01, *(uint32_t*)&c23);
        uint2 vpk = make_uint2(*(uint32_t*)&v01, *(uint32_t*)&v23);
        *(uint2*)&g_c[(size_t)(m0 + row) * DI + n0 + c4] = cpk;
        *(uint2*)&g_v[(size_t)(m0 + row) * DI + n0 + c4] = vpk;
    }

    // thread-serial chunk reduce: this tile IS one scan chunk (rows = time).
    // thread t<64: col t, rows 0-63 (earlier); t>=64: col t-64, rows 64-127.
    // Compose: C = C1*C2, V = C2*V1 + V2  (later o earlier).
    {
        const int batch = m0 >> 12;            // m0 / 4096
        const int chunk = (m0 & 4095) >> 7;    // (m0 % 4096) / 128
        const int col   = tid & 63;
        const int rb    = (tid >> 6) << 6;     // 0 or 64
        float C = 1.f, V = 0.f;
        #pragma unroll 8
        for (int r = 0; r < 64; r++) {
            float c_ = sc[(rb + r) * ESTR1 + col];
            float v_ = sv[(rb + r) * ESTR1 + col];
            V = fmaf(c_, V, v_);
            C *= c_;
        }
        if (tid >= 64) { sC2[col] = C; sV2[col] = V; }
        __syncthreads();
        if (tid < 64) {
            float C2 = sC2[col], V2 = sV2[col];
            int ch = batch * DI + n0 + col;
            g_chC[ch * NCHUNK + chunk] = C * C2;
            g_chV[ch * NCHUNK + chunk] = fmaf(C2, V, V2);
        }
    }
}

// ---- kernel 2: prefix over chunk aggregates + replay (2 channels/thread) ---
__global__ void k_scan_apply(const float* __restrict__ prev_hidden,
                             float* __restrict__ next_hidden) {
    int p = blockIdx.x * blockDim.x + threadIdx.x;   // pair 0..4095
    int chunk = blockIdx.y;
    int ch0 = p * 2;
    int b = ch0 >> 11, j = ch0 & (DI - 1);

    // chunk-start state via prefix over aggregates (redundant per block, cheap)
    float h0 = fmaxf(prev_hidden[ch0], 1e-8f);
    float h1 = fmaxf(prev_hidden[ch0 + 1], 1e-8f);
    #pragma unroll 1
    for (int k = 0; k < chunk; k++) {
        h0 = fmaf(g_chC[ch0 * NCHUNK + k], h0, g_chV[ch0 * NCHUNK + k]);
        h1 = fmaf(g_chC[(ch0 + 1) * NCHUNK + k], h1, g_chV[(ch0 + 1) * NCHUNK + k]);
    }

    size_t base2 = (((size_t)(b * TSEQ + chunk * CHLEN)) * DI + j) >> 1;  // half2 units
    const __half2* c2 = (const __half2*)g_c;
    const __half2* v2 = (const __half2*)g_v;
    __half2* hh2 = (__half2*)g_hh;
    #pragma unroll 4
    for (int t = 0; t < CHLEN; t++) {
        size_t o = base2 + (size_t)t * (DI / 2);
        float2 cf = __half22float2(c2[o]);
        float2 vf = __half22float2(v2[o]);
        h0 = fmaf(cf.x, h0, vf.x);
        h1 = fmaf(cf.y, h1, vf.y);
        hh2[o] = __floats2half2_rn(h0, h1);
    }
    if (chunk == NCHUNK - 1) {
        next_hidden[ch0]     = h0;
        next_hidden[ch0 + 1] = h1;
    }
}

// ---- kernel 3: GEMM2 out = h @ W_out (fp16 mma) ----------------------------
__device__ __forceinline__ void g2_load(int tid, int m0, int n0, int kt,
                                        __half* as, __half* bs) {
    const int k0 = kt * BK;
    #pragma unroll
    for (int q = 0; q < 8; q++) {
        int idx = tid + q * 128;
        int row = idx >> 3, c16 = (idx & 7) * 8;
        cp16(&as[row * STRH + c16], &g_hh[(size_t)(m0 + row) * DI + k0 + c16]);
    }
    #pragma unroll
    for (int q = 0; q < 8; q++) {
        int idx = tid + q * 128;
        int row = idx >> 3, c16 = (idx & 7) * 8;
        cp16(&bs[row * STRH + c16], &g_woT[(size_t)(n0 + row) * DI + k0 + c16]);
    }
}

__global__ void __launch_bounds__(128, 2) k_gemm2(float* __restrict__ out) {
    const int m0 = blockIdx.y * BM;
    const int n0 = blockIdx.x * 128;
    const int tid = threadIdx.x;
    const int wid = tid >> 5, lane = tid & 31;
    const int wm = wid & 1, wn = wid >> 1;       // 2 x 2 warp grid, 64x64 tiles
    const int grp = lane >> 2, tg = lane & 3;

    extern __shared__ char smraw[];
    __half* As = (__half*)smraw;
    __half* Bs = As + 2 * ATILE;

    float acc[4][8][4];
    #pragma unroll
    for (int a = 0; a < 4; a++)
        #pragma unroll
        for (int b = 0; b < 8; b++)
            #pragma unroll
            for (int r = 0; r < 4; r++) acc[a][b][r] = 0.f;

    const int a_row  = wm * 64 + (lane & 15);
    const int a_koff = (lane >> 4) << 3;
    const int b_row  = wn * 64 + (lane & 7) + ((lane >> 4) << 3);
    const int b_koff = ((lane >> 3) & 1) << 3;

    g2_load(tid, m0, n0, 0, As, Bs);
    CP_COMMIT();

    constexpr int NKT = DI / BK;                 // 32
    #pragma unroll 1
    for (int kt = 0; kt < NKT; kt++) {
        const int buf = kt & 1;
        if (kt + 1 < NKT) {
            g2_load(tid, m0, n0, kt + 1, As + (buf ^ 1) * ATILE, Bs + (buf ^ 1) * BTILE);
            CP_COMMIT();
            CP_WAIT1();
        } else {
            CP_WAIT0();
        }
        __syncthreads();
        const __half* as = As + buf * ATILE;
        const __half* bs = Bs + buf * BTILE;
        #pragma unroll
        for (int ks = 0; ks < 4; ks++) {
            const int k = ks * 16;
            uint32_t a[4][4], b[8][2];
            #pragma unroll
            for (int mm = 0; mm < 4; mm++)
                ldsm4(a[mm], &as[(a_row + mm * 16) * STRH + k + a_koff]);
            #pragma unroll
            for (int jp = 0; jp < 4; jp++) {
                uint32_t t[4];
                ldsm4(t, &bs[(b_row + jp * 16) * STRH + k + b_koff]);
                b[2 * jp][0] = t[0]; b[2 * jp][1] = t[1];
                b[2 * jp + 1][0] = t[2]; b[2 * jp + 1][1] = t[3];
            }
            #pragma unroll
            for (int mm = 0; mm < 4; mm++)
                #pragma unroll
                for (int jn = 0; jn < 8; jn++)
                    mma_f16(acc[mm][jn], a[mm], b[jn]);
        }
        __syncthreads();
    }

    // ---- epilogue: stage 128x128 tile in smem, coalesced float4 stores -----
    float* so = (float*)smraw;                 // [128][ESTR2]
    #pragma unroll
    for (int mm = 0; mm < 4; mm++)
        #pragma unroll
        for (int jn = 0; jn < 8; jn++)
            #pragma unroll
            for (int r = 0; r < 4; r++) {
                int rl = wm * 64 + mm * 16 + grp + ((r >> 1) << 3);
                int cl = wn * 64 + jn * 8 + tg * 2 + (r & 1);
                so[rl * ESTR2 + cl] = acc[mm][jn][r];
            }
    __syncthreads();
    #pragma unroll
    for (int q = 0; q < 32; q++) {
        int idx = tid + q * 128;               // 0..4095
        int row = idx >> 5, c4 = (idx & 31) * 4;
        float4 vv = *(const float4*)&so[row * ESTR2 + c4];
        *(float4*)&out[(size_t)(m0 + row) * DDIM + n0 + c4] = vv;
    }
}

// ---------------------------------------------------------------------------
extern "C" void kernel_launch(void* const* d_in, const int* in_sizes, int n_in,
                              void* d_out, int out_size) {
    const float* x    = (const float*)d_in[0];   // (4, 4096, 1024)
    const float* prev = (const float*)d_in[1];   // (4, 2048)
    const float* whg  = (const float*)d_in[2];   // (1024, 4096)
    const float* wout = (const float*)d_in[3];   // (2048, 1024)
    float* out = (float*)d_out;                  // out (16777216) + next_hidden (8192)
    float* next_hidden = out + (size_t)MROWS * DDIM;

    cudaFuncSetAttribute(k_gemm1, cudaFuncAttributeMaxDynamicSharedMemorySize, SMEM_GEMM_BYTES);
    cudaFuncSetAttribute(k_gemm2, cudaFuncAttributeMaxDynamicSharedMemorySize, SMEM_GEMM_BYTES);

    // 0) merged prep: x->fp16 + both weight transposes in ONE launch
    k_prep<<<NCX + NWT + NOT_, 256>>>(x, whg, wout);
    // 1) GEMM1 (fp16 mma) + fp16 c/v epilogue + thread-serial chunk reduce
    {
        dim3 grid(DI / 64, MROWS / BM);          // 32 x 128
        k_gemm1<<<grid, 128, SMEM_GEMM_BYTES>>>();
    }
    // 2) prefix + replay -> h (fp16), next_hidden
    {
        dim3 grid((NCHAN / 2) / 256, NCHUNK);    // 16 x 32
        k_scan_apply<<<grid, 256>>>(prev, next_hidden);
    }
    // 3) GEMM2 (fp16 mma) -> out
    {
        dim3 grid(DDIM / 128, MROWS / BM);       // 8 x 128
        k_gemm2<<<grid, 128, SMEM_GEMM_BYTES>>>(out);
    }
}